// round 15
// baseline (speedup 1.0000x reference)
#include <cuda_runtime.h>
#include <math.h>

// TropicalAffine: LayerNorm -> max-plus matmul -> max(., bias)
// Exact candidate-pruned tropical matmul, three-kernel pipeline.
//   S_b = {k : xn[b,k] > TAU}; est over S_b; certificate:
//   excluded contribution <= TAU + colmax_W[i] (sound in fp32 by rounding
//   monotonicity); failing elements queued globally, re-solved exactly by
//   a separate fully-parallel cleanup kernel.
// R13: R11's measured-best tropical core (256 thr, 4 rows/block, 48 regs,
//   5 blocks/SM) made PERSISTENT: grid = 740 = one full wave; blocks pull
//   group indices from an atomic counter, killing the 1.38-wave tail
//   (~35us of SM idle measured-implied in R11).

#define Bn 4096
#define Fn 1024
#define CAP 224
#define TAU 1.05f
#define LN_EPS 1e-5f
#define QCAP 262144
#define NGROUP (Bn / 4)
#define PGRID 740

__device__ float    g_xn[Bn * Fn];        // layernorm output
__device__ float2   g_cand[Bn * CAP];     // (xn value, k*(Fn/4) as int bits)
__device__ int      g_cnt[Bn];            // padded (even) candidate count
__device__ unsigned g_cmax_enc[Fn];       // column max of W (encoded)
__device__ int      g_qcnt;               // cleanup queue count
__device__ int      g_queue[QCAP];        // failing element indices b*Fn+i
__device__ int      g_work;               // persistent work counter

// Order-preserving float<->uint encoding: f1 < f2  <=>  enc(f1) < enc(f2).
__device__ __forceinline__ unsigned enc_f(float f) {
    unsigned u = __float_as_uint(f);
    return (u & 0x80000000u) ? ~u : (u | 0x80000000u);
}
__device__ __forceinline__ float dec_f(unsigned u) {
    return (u & 0x80000000u) ? __uint_as_float(u & 0x7FFFFFFFu)
                             : __uint_as_float(~u);
}

// ---------------------------------------------------------------------------
// Kernel 1: fused LayerNorm+compaction (blocks 0..Bn-1) and parallel
// column-max of W (blocks Bn..Bn+127). Block Bn also resets counters.
// ---------------------------------------------------------------------------
__global__ __launch_bounds__(256) void prep_kernel(
    const float* __restrict__ x,
    const float* __restrict__ W,
    const float* __restrict__ gamma,
    const float* __restrict__ beta)
{
    if (blockIdx.x >= Bn) {
        const int idx = blockIdx.x - Bn;      // 0..127
        if (idx == 0 && threadIdx.x == 0) { g_qcnt = 0; g_work = 0; }
        const int kc = idx >> 2;              // 0..31 (32-row slice)
        const int i  = (idx & 3) * 256 + threadIdx.x;
        const int k0 = kc * 32;
        float m = -INFINITY;
        #pragma unroll 8
        for (int k = k0; k < k0 + 32; k++)
            m = fmaxf(m, W[(size_t)k * Fn + i]);
        atomicMax(&g_cmax_enc[i], enc_f(m));  // idempotent across replays
        return;
    }

    const int b    = blockIdx.x;
    const int tid  = threadIdx.x;
    const int warp = tid >> 5, lane = tid & 31;

    __shared__ float ws[8], wq[8];
    __shared__ float s_mu, s_rs;
    __shared__ int   wsum[8], wbase[8], s_tot;

    float4 v = ((const float4*)(x + (size_t)b * Fn))[tid];
    float s = v.x + v.y + v.z + v.w;
    float q = v.x * v.x + v.y * v.y + v.z * v.z + v.w * v.w;

    #pragma unroll
    for (int o = 16; o > 0; o >>= 1) {
        s += __shfl_xor_sync(0xFFFFFFFFu, s, o);
        q += __shfl_xor_sync(0xFFFFFFFFu, q, o);
    }
    if (lane == 0) { ws[warp] = s; wq[warp] = q; }
    __syncthreads();

    if (tid == 0) {
        float ts = 0.f, tq = 0.f;
        #pragma unroll
        for (int i = 0; i < 8; i++) { ts += ws[i]; tq += wq[i]; }
        float mu  = ts * (1.0f / Fn);
        float var = tq * (1.0f / Fn) - mu * mu;
        s_mu = mu;
        s_rs = rsqrtf(var + LN_EPS);
    }
    __syncthreads();

    const float mu = s_mu, rs = s_rs;
    float4 g  = ((const float4*)gamma)[tid];
    float4 be = ((const float4*)beta)[tid];

    float xn[4];
    xn[0] = (v.x - mu) * rs * g.x + be.x;
    xn[1] = (v.y - mu) * rs * g.y + be.y;
    xn[2] = (v.z - mu) * rs * g.z + be.z;
    xn[3] = (v.w - mu) * rs * g.w + be.w;

    ((float4*)(g_xn + (size_t)b * Fn))[tid] =
        make_float4(xn[0], xn[1], xn[2], xn[3]);

    unsigned f = 0u;
    #pragma unroll
    for (int j = 0; j < 4; j++)
        if (xn[j] > TAU) f |= (1u << j);
    int pcnt = __popc(f);

    int inc = pcnt;
    #pragma unroll
    for (int o = 1; o < 32; o <<= 1) {
        int t = __shfl_up_sync(0xFFFFFFFFu, inc, o);
        if (lane >= o) inc += t;
    }
    int exclw = inc - pcnt;
    if (lane == 31) wsum[warp] = inc;
    __syncthreads();
    if (tid == 0) {
        int run = 0;
        #pragma unroll
        for (int i = 0; i < 8; i++) { wbase[i] = run; run += wsum[i]; }
        s_tot = run;
    }
    __syncthreads();

    float2* cand = g_cand + (size_t)b * CAP;
    int pos = wbase[warp] + exclw;
    const int kb = tid * 4;
    #pragma unroll
    for (int j = 0; j < 4; j++) {
        if ((f >> j) & 1) {
            if (pos < CAP)
                cand[pos] = make_float2(xn[j],
                                        __int_as_float((kb + j) * (Fn / 4)));
            pos++;
        }
    }

    const int tot = s_tot;
    if (tot >= CAP) {   // overflow: est=-INF -> every column queued -> exact
        if (tid == 0) g_cnt[b] = 0;
    } else {
        const int totp = (tot + 1) & ~1;   // pad to even with -INF sentinel
        if (tid == 0) {
            if (totp != tot)
                cand[tot] = make_float2(-INFINITY, __int_as_float(0));
            g_cnt[b] = totp;
        }
    }
}

// ---------------------------------------------------------------------------
// Kernel 2: persistent pruned tropical matmul. 256 thr = 8 warps = 4 rows
// per group; warp w: row = w>>1, column half = w&1. Thread owns 16 cols:
// i = h*512 + c*128 + lane*4, c=0..3. Blocks loop over groups via g_work.
// ---------------------------------------------------------------------------
__global__ __launch_bounds__(256, 5) void tropical_kernel(
    const float* __restrict__ W,
    const float* __restrict__ bias,
    float* __restrict__ out)
{
    const int tid  = threadIdx.x;
    const int wid  = tid >> 5;
    const int lane = tid & 31;
    const int r    = wid >> 1;          // row within group (0..3)
    const int h    = wid & 1;           // column half

    __shared__ float2 s_cand[4][CAP];   // 7 KB
    __shared__ int    s_g;

    const float4* Wb = (const float4*)W + h * 128 + lane;

    for (;;) {
        if (tid == 0) s_g = atomicAdd(&g_work, 1);
        __syncthreads();
        const int g = s_g;
        if (g >= NGROUP) break;
        const int b = g * 4 + r;

        const int cnt = g_cnt[b];           // even
        for (int j = (tid & 63); j < cnt; j += 64)
            s_cand[r][j] = g_cand[(size_t)b * CAP + j];
        __syncthreads();

        float a[4][4];
        #pragma unroll
        for (int c = 0; c < 4; c++)
            #pragma unroll
            for (int e = 0; e < 4; e++) a[c][e] = -INFINITY;

        for (int j = 0; j < cnt; j += 2) {
            float4 ee = *(const float4*)&s_cand[r][j];   // 1 LDS.128 = 2 entries
            const float4* p0 = Wb + __float_as_int(ee.y);
            const float4* p1 = Wb + __float_as_int(ee.w);
            const float s0 = ee.x, s1 = ee.z;
            float4 u0 = p0[0], u1 = p0[32], u2 = p0[64], u3 = p0[96];
            float4 w0 = p1[0], w1 = p1[32], w2 = p1[64], w3 = p1[96];
            a[0][0] = fmaxf(a[0][0], s0 + u0.x);
            a[0][1] = fmaxf(a[0][1], s0 + u0.y);
            a[0][2] = fmaxf(a[0][2], s0 + u0.z);
            a[0][3] = fmaxf(a[0][3], s0 + u0.w);
            a[1][0] = fmaxf(a[1][0], s0 + u1.x);
            a[1][1] = fmaxf(a[1][1], s0 + u1.y);
            a[1][2] = fmaxf(a[1][2], s0 + u1.z);
            a[1][3] = fmaxf(a[1][3], s0 + u1.w);
            a[2][0] = fmaxf(a[2][0], s0 + u2.x);
            a[2][1] = fmaxf(a[2][1], s0 + u2.y);
            a[2][2] = fmaxf(a[2][2], s0 + u2.z);
            a[2][3] = fmaxf(a[2][3], s0 + u2.w);
            a[3][0] = fmaxf(a[3][0], s0 + u3.x);
            a[3][1] = fmaxf(a[3][1], s0 + u3.y);
            a[3][2] = fmaxf(a[3][2], s0 + u3.z);
            a[3][3] = fmaxf(a[3][3], s0 + u3.w);
            a[0][0] = fmaxf(a[0][0], s1 + w0.x);
            a[0][1] = fmaxf(a[0][1], s1 + w0.y);
            a[0][2] = fmaxf(a[0][2], s1 + w0.z);
            a[0][3] = fmaxf(a[0][3], s1 + w0.w);
            a[1][0] = fmaxf(a[1][0], s1 + w1.x);
            a[1][1] = fmaxf(a[1][1], s1 + w1.y);
            a[1][2] = fmaxf(a[1][2], s1 + w1.z);
            a[1][3] = fmaxf(a[1][3], s1 + w1.w);
            a[2][0] = fmaxf(a[2][0], s1 + w2.x);
            a[2][1] = fmaxf(a[2][1], s1 + w2.y);
            a[2][2] = fmaxf(a[2][2], s1 + w2.z);
            a[2][3] = fmaxf(a[2][3], s1 + w2.w);
            a[3][0] = fmaxf(a[3][0], s1 + w3.x);
            a[3][1] = fmaxf(a[3][1], s1 + w3.y);
            a[3][2] = fmaxf(a[3][2], s1 + w3.z);
            a[3][3] = fmaxf(a[3][3], s1 + w3.w);
        }

        // Certificate (decode cmax) + queue push + tropical bias + store.
        float* orow = out + (size_t)b * Fn;
        #pragma unroll
        for (int c = 0; c < 4; c++) {
            const int i = h * 512 + c * 128 + lane * 4;
            uint4 cme = *(const uint4*)(g_cmax_enc + i);
            const float th[4] = {TAU + dec_f(cme.x), TAU + dec_f(cme.y),
                                 TAU + dec_f(cme.z), TAU + dec_f(cme.w)};
            #pragma unroll
            for (int e = 0; e < 4; e++) {
                if (a[c][e] < th[e]) {
                    int qp = atomicAdd(&g_qcnt, 1);
                    if (qp < QCAP) g_queue[qp] = b * Fn + (i + e);
                }
            }
            float4 bb = *(const float4*)(bias + i);
            *(float4*)(orow + i) = make_float4(fmaxf(a[c][0], bb.x),
                                               fmaxf(a[c][1], bb.y),
                                               fmaxf(a[c][2], bb.z),
                                               fmaxf(a[c][3], bb.w));
        }
        __syncthreads();   // protect s_cand/s_g before next group
    }
}

// ---------------------------------------------------------------------------
// Kernel 3: exact cleanup. One warp per queued element; lane-parallel scan.
// ---------------------------------------------------------------------------
__global__ __launch_bounds__(128) void cleanup_kernel(
    const float* __restrict__ W,
    const float* __restrict__ bias,
    float* __restrict__ out)
{
    const int lane  = threadIdx.x & 31;
    const int warpg = (blockIdx.x * blockDim.x + threadIdx.x) >> 5;
    const int nwarp = (gridDim.x * blockDim.x) >> 5;
    const int qn    = min(g_qcnt, QCAP);

    for (int e = warpg; e < qn; e += nwarp) {
        const int idx = g_queue[e];
        const int b = idx >> 10, i = idx & (Fn - 1);
        const float* xrow = g_xn + (size_t)b * Fn;
        const float* wc   = W + i;
        float m = -INFINITY;
        for (int k = lane; k < Fn; k += 32)
            m = fmaxf(m, xrow[k] + wc[(size_t)k * Fn]);
        #pragma unroll
        for (int o = 16; o > 0; o >>= 1)
            m = fmaxf(m, __shfl_xor_sync(0xFFFFFFFFu, m, o));
        if (lane == 0)
            out[idx] = fmaxf(m, bias[i]);
    }
}

// ---------------------------------------------------------------------------
extern "C" void kernel_launch(void* const* d_in, const int* in_sizes, int n_in,
                              void* d_out, int out_size)
{
    const float* x     = (const float*)d_in[0];
    const float* W     = (const float*)d_in[1];
    const float* bvec  = (const float*)d_in[2];
    const float* gamma = (const float*)d_in[3];
    const float* beta  = (const float*)d_in[4];
    float* out = (float*)d_out;

    prep_kernel<<<Bn + 128, 256>>>(x, W, gamma, beta);
    tropical_kernel<<<PGRID, 256>>>(W, bvec, out);
    cleanup_kernel<<<1024, 128>>>(W, bvec, out);
}

// round 16
// speedup vs baseline: 1.3630x; 1.3630x over previous
#include <cuda_runtime.h>
#include <math.h>

// TropicalAffine: LayerNorm -> max-plus matmul -> max(., bias)
// Exact candidate-pruned tropical matmul, three-kernel pipeline.
//   S_b = {k : xn[b,k] > TAU}; est over S_b; certificate:
//   excluded contribution <= TAU + colmax_W[i] (sound in fp32 by rounding
//   monotonicity); failing elements queued globally, re-solved exactly by
//   a separate fully-parallel cleanup kernel.
// R14: revert persistence (R13 regressed +170us). R11 config with
//   launch_bounds(256,6): 6 blocks/SM -> 888 slots (1.15 waves, was 1.38)
//   and 48 resident warps. Inner loop staged as 2x4 loads (16 transient
//   regs, R4-measured 40-reg shape) to fit the 42-reg cap without spills.

#define Bn 4096
#define Fn 1024
#define CAP 224
#define TAU 1.05f
#define LN_EPS 1e-5f
#define QCAP 262144

__device__ float    g_xn[Bn * Fn];        // layernorm output
__device__ float2   g_cand[Bn * CAP];     // (xn value, k*(Fn/4) as int bits)
__device__ int      g_cnt[Bn];            // padded (even) candidate count
__device__ unsigned g_cmax_enc[Fn];       // column max of W (encoded)
__device__ int      g_qcnt;               // cleanup queue count
__device__ int      g_queue[QCAP];        // failing element indices b*Fn+i

// Order-preserving float<->uint encoding: f1 < f2  <=>  enc(f1) < enc(f2).
__device__ __forceinline__ unsigned enc_f(float f) {
    unsigned u = __float_as_uint(f);
    return (u & 0x80000000u) ? ~u : (u | 0x80000000u);
}
__device__ __forceinline__ float dec_f(unsigned u) {
    return (u & 0x80000000u) ? __uint_as_float(u & 0x7FFFFFFFu)
                             : __uint_as_float(~u);
}

// ---------------------------------------------------------------------------
// Kernel 1: fused LayerNorm+compaction (blocks 0..Bn-1) and parallel
// column-max of W (blocks Bn..Bn+127). Block Bn also resets g_qcnt.
// ---------------------------------------------------------------------------
__global__ __launch_bounds__(256) void prep_kernel(
    const float* __restrict__ x,
    const float* __restrict__ W,
    const float* __restrict__ gamma,
    const float* __restrict__ beta)
{
    if (blockIdx.x >= Bn) {
        const int idx = blockIdx.x - Bn;      // 0..127
        if (idx == 0 && threadIdx.x == 0) g_qcnt = 0;
        const int kc = idx >> 2;              // 0..31 (32-row slice)
        const int i  = (idx & 3) * 256 + threadIdx.x;
        const int k0 = kc * 32;
        float m = -INFINITY;
        #pragma unroll 8
        for (int k = k0; k < k0 + 32; k++)
            m = fmaxf(m, W[(size_t)k * Fn + i]);
        atomicMax(&g_cmax_enc[i], enc_f(m));  // idempotent across replays
        return;
    }

    const int b    = blockIdx.x;
    const int tid  = threadIdx.x;
    const int warp = tid >> 5, lane = tid & 31;

    __shared__ float ws[8], wq[8];
    __shared__ float s_mu, s_rs;
    __shared__ int   wsum[8], wbase[8], s_tot;

    float4 v = ((const float4*)(x + (size_t)b * Fn))[tid];
    float s = v.x + v.y + v.z + v.w;
    float q = v.x * v.x + v.y * v.y + v.z * v.z + v.w * v.w;

    #pragma unroll
    for (int o = 16; o > 0; o >>= 1) {
        s += __shfl_xor_sync(0xFFFFFFFFu, s, o);
        q += __shfl_xor_sync(0xFFFFFFFFu, q, o);
    }
    if (lane == 0) { ws[warp] = s; wq[warp] = q; }
    __syncthreads();

    if (tid == 0) {
        float ts = 0.f, tq = 0.f;
        #pragma unroll
        for (int i = 0; i < 8; i++) { ts += ws[i]; tq += wq[i]; }
        float mu  = ts * (1.0f / Fn);
        float var = tq * (1.0f / Fn) - mu * mu;
        s_mu = mu;
        s_rs = rsqrtf(var + LN_EPS);
    }
    __syncthreads();

    const float mu = s_mu, rs = s_rs;
    float4 g  = ((const float4*)gamma)[tid];
    float4 be = ((const float4*)beta)[tid];

    float xn[4];
    xn[0] = (v.x - mu) * rs * g.x + be.x;
    xn[1] = (v.y - mu) * rs * g.y + be.y;
    xn[2] = (v.z - mu) * rs * g.z + be.z;
    xn[3] = (v.w - mu) * rs * g.w + be.w;

    ((float4*)(g_xn + (size_t)b * Fn))[tid] =
        make_float4(xn[0], xn[1], xn[2], xn[3]);

    unsigned f = 0u;
    #pragma unroll
    for (int j = 0; j < 4; j++)
        if (xn[j] > TAU) f |= (1u << j);
    int pcnt = __popc(f);

    int inc = pcnt;
    #pragma unroll
    for (int o = 1; o < 32; o <<= 1) {
        int t = __shfl_up_sync(0xFFFFFFFFu, inc, o);
        if (lane >= o) inc += t;
    }
    int exclw = inc - pcnt;
    if (lane == 31) wsum[warp] = inc;
    __syncthreads();
    if (tid == 0) {
        int run = 0;
        #pragma unroll
        for (int i = 0; i < 8; i++) { wbase[i] = run; run += wsum[i]; }
        s_tot = run;
    }
    __syncthreads();

    float2* cand = g_cand + (size_t)b * CAP;
    int pos = wbase[warp] + exclw;
    const int kb = tid * 4;
    #pragma unroll
    for (int j = 0; j < 4; j++) {
        if ((f >> j) & 1) {
            if (pos < CAP)
                cand[pos] = make_float2(xn[j],
                                        __int_as_float((kb + j) * (Fn / 4)));
            pos++;
        }
    }

    const int tot = s_tot;
    if (tot >= CAP) {   // overflow: est=-INF -> every column queued -> exact
        if (tid == 0) g_cnt[b] = 0;
    } else {
        const int totp = (tot + 1) & ~1;   // pad to even with -INF sentinel
        if (tid == 0) {
            if (totp != tot)
                cand[tot] = make_float2(-INFINITY, __int_as_float(0));
            g_cnt[b] = totp;
        }
    }
}

// ---------------------------------------------------------------------------
// Kernel 2: pruned tropical matmul. 256 thr = 8 warps = 4 rows/block;
// warp w: row = w>>1, column half = w&1. Thread owns 16 cols:
// i = h*512 + c*128 + lane*4, c=0..3. 6 blocks/SM -> 48 warps, 1.15 waves.
// Candidate pair read via one LDS.128, consumed as two 4-load groups
// (16 transient regs) to fit the 42-reg cap.
// ---------------------------------------------------------------------------
__global__ __launch_bounds__(256, 6) void tropical_kernel(
    const float* __restrict__ W,
    const float* __restrict__ bias,
    float* __restrict__ out)
{
    const int g    = blockIdx.x;
    const int tid  = threadIdx.x;
    const int wid  = tid >> 5;
    const int lane = tid & 31;
    const int r    = wid >> 1;          // row within block (0..3)
    const int h    = wid & 1;           // column half
    const int b    = g * 4 + r;

    __shared__ float2 s_cand[4][CAP];   // 7 KB

    const int cnt = g_cnt[b];           // even
    for (int j = (tid & 63); j < cnt; j += 64)
        s_cand[r][j] = g_cand[(size_t)b * CAP + j];
    __syncthreads();

    float a[4][4];
    #pragma unroll
    for (int c = 0; c < 4; c++)
        #pragma unroll
        for (int e = 0; e < 4; e++) a[c][e] = -INFINITY;

    const float4* Wb = (const float4*)W + h * 128 + lane;

    for (int j = 0; j < cnt; j += 2) {
        float4 ee = *(const float4*)&s_cand[r][j];   // two entries, 1 LDS.128
        const float4* p0 = Wb + __float_as_int(ee.y);
        const float4* p1 = Wb + __float_as_int(ee.w);
        const float s0 = ee.x, s1 = ee.z;
        // Group 1: candidate 0 (4 loads staged, 16 fmax-pairs)
        {
            float4 u0 = p0[0], u1 = p0[32], u2 = p0[64], u3 = p0[96];
            a[0][0] = fmaxf(a[0][0], s0 + u0.x);
            a[0][1] = fmaxf(a[0][1], s0 + u0.y);
            a[0][2] = fmaxf(a[0][2], s0 + u0.z);
            a[0][3] = fmaxf(a[0][3], s0 + u0.w);
            a[1][0] = fmaxf(a[1][0], s0 + u1.x);
            a[1][1] = fmaxf(a[1][1], s0 + u1.y);
            a[1][2] = fmaxf(a[1][2], s0 + u1.z);
            a[1][3] = fmaxf(a[1][3], s0 + u1.w);
            a[2][0] = fmaxf(a[2][0], s0 + u2.x);
            a[2][1] = fmaxf(a[2][1], s0 + u2.y);
            a[2][2] = fmaxf(a[2][2], s0 + u2.z);
            a[2][3] = fmaxf(a[2][3], s0 + u2.w);
            a[3][0] = fmaxf(a[3][0], s0 + u3.x);
            a[3][1] = fmaxf(a[3][1], s0 + u3.y);
            a[3][2] = fmaxf(a[3][2], s0 + u3.z);
            a[3][3] = fmaxf(a[3][3], s0 + u3.w);
        }
        // Group 2: candidate 1
        {
            float4 w0 = p1[0], w1 = p1[32], w2 = p1[64], w3 = p1[96];
            a[0][0] = fmaxf(a[0][0], s1 + w0.x);
            a[0][1] = fmaxf(a[0][1], s1 + w0.y);
            a[0][2] = fmaxf(a[0][2], s1 + w0.z);
            a[0][3] = fmaxf(a[0][3], s1 + w0.w);
            a[1][0] = fmaxf(a[1][0], s1 + w1.x);
            a[1][1] = fmaxf(a[1][1], s1 + w1.y);
            a[1][2] = fmaxf(a[1][2], s1 + w1.z);
            a[1][3] = fmaxf(a[1][3], s1 + w1.w);
            a[2][0] = fmaxf(a[2][0], s1 + w2.x);
            a[2][1] = fmaxf(a[2][1], s1 + w2.y);
            a[2][2] = fmaxf(a[2][2], s1 + w2.z);
            a[2][3] = fmaxf(a[2][3], s1 + w2.w);
            a[3][0] = fmaxf(a[3][0], s1 + w3.x);
            a[3][1] = fmaxf(a[3][1], s1 + w3.y);
            a[3][2] = fmaxf(a[3][2], s1 + w3.z);
            a[3][3] = fmaxf(a[3][3], s1 + w3.w);
        }
    }

    // Certificate (decode cmax) + global queue push + tropical bias + store.
    float* orow = out + (size_t)b * Fn;
    #pragma unroll
    for (int c = 0; c < 4; c++) {
        const int i = h * 512 + c * 128 + lane * 4;
        uint4 cme = *(const uint4*)(g_cmax_enc + i);
        const float th[4] = {TAU + dec_f(cme.x), TAU + dec_f(cme.y),
                             TAU + dec_f(cme.z), TAU + dec_f(cme.w)};
        #pragma unroll
        for (int e = 0; e < 4; e++) {
            if (a[c][e] < th[e]) {
                int qp = atomicAdd(&g_qcnt, 1);
                if (qp < QCAP) g_queue[qp] = b * Fn + (i + e);
            }
        }
        float4 bb = *(const float4*)(bias + i);
        *(float4*)(orow + i) = make_float4(fmaxf(a[c][0], bb.x),
                                           fmaxf(a[c][1], bb.y),
                                           fmaxf(a[c][2], bb.z),
                                           fmaxf(a[c][3], bb.w));
    }
}

// ---------------------------------------------------------------------------
// Kernel 3: exact cleanup. One warp per queued element; lane-parallel scan.
// ---------------------------------------------------------------------------
__global__ __launch_bounds__(128) void cleanup_kernel(
    const float* __restrict__ W,
    const float* __restrict__ bias,
    float* __restrict__ out)
{
    const int lane  = threadIdx.x & 31;
    const int warpg = (blockIdx.x * blockDim.x + threadIdx.x) >> 5;
    const int nwarp = (gridDim.x * blockDim.x) >> 5;
    const int qn    = min(g_qcnt, QCAP);

    for (int e = warpg; e < qn; e += nwarp) {
        const int idx = g_queue[e];
        const int b = idx >> 10, i = idx & (Fn - 1);
        const float* xrow = g_xn + (size_t)b * Fn;
        const float* wc   = W + i;
        float m = -INFINITY;
        for (int k = lane; k < Fn; k += 32)
            m = fmaxf(m, xrow[k] + wc[(size_t)k * Fn]);
        #pragma unroll
        for (int o = 16; o > 0; o >>= 1)
            m = fmaxf(m, __shfl_xor_sync(0xFFFFFFFFu, m, o));
        if (lane == 0)
            out[idx] = fmaxf(m, bias[i]);
    }
}

// ---------------------------------------------------------------------------
extern "C" void kernel_launch(void* const* d_in, const int* in_sizes, int n_in,
                              void* d_out, int out_size)
{
    const float* x     = (const float*)d_in[0];
    const float* W     = (const float*)d_in[1];
    const float* bvec  = (const float*)d_in[2];
    const float* gamma = (const float*)d_in[3];
    const float* beta  = (const float*)d_in[4];
    float* out = (float*)d_out;

    prep_kernel<<<Bn + 128, 256>>>(x, W, gamma, beta);
    tropical_kernel<<<Bn / 4, 256>>>(W, bvec, out);
    cleanup_kernel<<<1024, 128>>>(W, bvec, out);
}

// round 17
// speedup vs baseline: 1.7664x; 1.2959x over previous
#include <cuda_runtime.h>
#include <math.h>

// TropicalAffine: LayerNorm -> max-plus matmul -> max(., bias)
// Exact candidate-pruned tropical matmul, three-kernel pipeline.
//   S_b = {k : xn[b,k] > TAU}; est over S_b; certificate:
//   excluded contribution <= TAU + colmax_W[i] (sound in fp32 by rounding
//   monotonicity); failing elements queued globally, re-solved exactly by
//   a separate fully-parallel cleanup kernel.
// R15: tropical kernel restored BYTE-IDENTICAL to R11 (measured best,
//   200.8 total; every structural perturbation since regressed).
//   TAU 1.05 -> 1.00 per two-point measured failure fit (240K@1.4,
//   ~6.5K@1.05, x1.74 per 0.05): failures ~4K, cleanup ~10us, tropical
//   +1-2us (candidates ride nearly free in the latency-bound regime).
//   Cleanup grid doubled to drain the queue with less tail.

#define Bn 4096
#define Fn 1024
#define CAP 224
#define TAU 1.00f
#define LN_EPS 1e-5f
#define QCAP 262144

__device__ float    g_xn[Bn * Fn];        // layernorm output
__device__ float2   g_cand[Bn * CAP];     // (xn value, k*(Fn/4) as int bits)
__device__ int      g_cnt[Bn];            // padded (even) candidate count
__device__ unsigned g_cmax_enc[Fn];       // column max of W (encoded)
__device__ int      g_qcnt;               // cleanup queue count
__device__ int      g_queue[QCAP];        // failing element indices b*Fn+i

// Order-preserving float<->uint encoding: f1 < f2  <=>  enc(f1) < enc(f2).
__device__ __forceinline__ unsigned enc_f(float f) {
    unsigned u = __float_as_uint(f);
    return (u & 0x80000000u) ? ~u : (u | 0x80000000u);
}
__device__ __forceinline__ float dec_f(unsigned u) {
    return (u & 0x80000000u) ? __uint_as_float(u & 0x7FFFFFFFu)
                             : __uint_as_float(~u);
}

// ---------------------------------------------------------------------------
// Kernel 1: fused LayerNorm+compaction (blocks 0..Bn-1) and parallel
// column-max of W (blocks Bn..Bn+127). Block Bn also resets g_qcnt.
// ---------------------------------------------------------------------------
__global__ __launch_bounds__(256) void prep_kernel(
    const float* __restrict__ x,
    const float* __restrict__ W,
    const float* __restrict__ gamma,
    const float* __restrict__ beta)
{
    if (blockIdx.x >= Bn) {
        const int idx = blockIdx.x - Bn;      // 0..127
        if (idx == 0 && threadIdx.x == 0) g_qcnt = 0;
        const int kc = idx >> 2;              // 0..31 (32-row slice)
        const int i  = (idx & 3) * 256 + threadIdx.x;
        const int k0 = kc * 32;
        float m = -INFINITY;
        #pragma unroll 8
        for (int k = k0; k < k0 + 32; k++)
            m = fmaxf(m, W[(size_t)k * Fn + i]);
        atomicMax(&g_cmax_enc[i], enc_f(m));  // idempotent across replays
        return;
    }

    const int b    = blockIdx.x;
    const int tid  = threadIdx.x;
    const int warp = tid >> 5, lane = tid & 31;

    __shared__ float ws[8], wq[8];
    __shared__ float s_mu, s_rs;
    __shared__ int   wsum[8], wbase[8], s_tot;

    float4 v = ((const float4*)(x + (size_t)b * Fn))[tid];
    float s = v.x + v.y + v.z + v.w;
    float q = v.x * v.x + v.y * v.y + v.z * v.z + v.w * v.w;

    #pragma unroll
    for (int o = 16; o > 0; o >>= 1) {
        s += __shfl_xor_sync(0xFFFFFFFFu, s, o);
        q += __shfl_xor_sync(0xFFFFFFFFu, q, o);
    }
    if (lane == 0) { ws[warp] = s; wq[warp] = q; }
    __syncthreads();

    if (tid == 0) {
        float ts = 0.f, tq = 0.f;
        #pragma unroll
        for (int i = 0; i < 8; i++) { ts += ws[i]; tq += wq[i]; }
        float mu  = ts * (1.0f / Fn);
        float var = tq * (1.0f / Fn) - mu * mu;
        s_mu = mu;
        s_rs = rsqrtf(var + LN_EPS);
    }
    __syncthreads();

    const float mu = s_mu, rs = s_rs;
    float4 g  = ((const float4*)gamma)[tid];
    float4 be = ((const float4*)beta)[tid];

    float xn[4];
    xn[0] = (v.x - mu) * rs * g.x + be.x;
    xn[1] = (v.y - mu) * rs * g.y + be.y;
    xn[2] = (v.z - mu) * rs * g.z + be.z;
    xn[3] = (v.w - mu) * rs * g.w + be.w;

    ((float4*)(g_xn + (size_t)b * Fn))[tid] =
        make_float4(xn[0], xn[1], xn[2], xn[3]);

    unsigned f = 0u;
    #pragma unroll
    for (int j = 0; j < 4; j++)
        if (xn[j] > TAU) f |= (1u << j);
    int pcnt = __popc(f);

    int inc = pcnt;
    #pragma unroll
    for (int o = 1; o < 32; o <<= 1) {
        int t = __shfl_up_sync(0xFFFFFFFFu, inc, o);
        if (lane >= o) inc += t;
    }
    int exclw = inc - pcnt;
    if (lane == 31) wsum[warp] = inc;
    __syncthreads();
    if (tid == 0) {
        int run = 0;
        #pragma unroll
        for (int i = 0; i < 8; i++) { wbase[i] = run; run += wsum[i]; }
        s_tot = run;
    }
    __syncthreads();

    float2* cand = g_cand + (size_t)b * CAP;
    int pos = wbase[warp] + exclw;
    const int kb = tid * 4;
    #pragma unroll
    for (int j = 0; j < 4; j++) {
        if ((f >> j) & 1) {
            if (pos < CAP)
                cand[pos] = make_float2(xn[j],
                                        __int_as_float((kb + j) * (Fn / 4)));
            pos++;
        }
    }

    const int tot = s_tot;
    if (tot >= CAP) {   // overflow: est=-INF -> every column queued -> exact
        if (tid == 0) g_cnt[b] = 0;
    } else {
        const int totp = (tot + 1) & ~1;   // pad to even with -INF sentinel
        if (tid == 0) {
            if (totp != tot)
                cand[tot] = make_float2(-INFINITY, __int_as_float(0));
            g_cnt[b] = totp;
        }
    }
}

// ---------------------------------------------------------------------------
// Kernel 2: pruned tropical matmul (byte-identical to R11's measured-best).
// 256 thr = 8 warps = 4 rows/block; warp w: row = w>>1, column half = w&1.
// Thread owns 16 cols: i = h*512 + c*128 + lane*4, c=0..3.
// ---------------------------------------------------------------------------
__global__ __launch_bounds__(256, 5) void tropical_kernel(
    const float* __restrict__ W,
    const float* __restrict__ bias,
    float* __restrict__ out)
{
    const int g    = blockIdx.x;
    const int tid  = threadIdx.x;
    const int wid  = tid >> 5;
    const int lane = tid & 31;
    const int r    = wid >> 1;          // row within block (0..3)
    const int h    = wid & 1;           // column half
    const int b    = g * 4 + r;

    __shared__ float2 s_cand[4][CAP];   // 7 KB

    const int cnt = g_cnt[b];           // even
    for (int j = (tid & 63); j < cnt; j += 64)
        s_cand[r][j] = g_cand[(size_t)b * CAP + j];
    __syncthreads();

    float a[4][4];
    #pragma unroll
    for (int c = 0; c < 4; c++)
        #pragma unroll
        for (int e = 0; e < 4; e++) a[c][e] = -INFINITY;

    const float4* Wb = (const float4*)W + h * 128 + lane;

    for (int j = 0; j < cnt; j += 2) {
        float4 ee = *(const float4*)&s_cand[r][j];   // two entries, 1 LDS.128
        const float4* p0 = Wb + __float_as_int(ee.y);
        const float4* p1 = Wb + __float_as_int(ee.w);
        const float s0 = ee.x, s1 = ee.z;
        float4 u0 = p0[0], u1 = p0[32], u2 = p0[64], u3 = p0[96];
        float4 w0 = p1[0], w1 = p1[32], w2 = p1[64], w3 = p1[96];
        a[0][0] = fmaxf(a[0][0], s0 + u0.x);
        a[0][1] = fmaxf(a[0][1], s0 + u0.y);
        a[0][2] = fmaxf(a[0][2], s0 + u0.z);
        a[0][3] = fmaxf(a[0][3], s0 + u0.w);
        a[1][0] = fmaxf(a[1][0], s0 + u1.x);
        a[1][1] = fmaxf(a[1][1], s0 + u1.y);
        a[1][2] = fmaxf(a[1][2], s0 + u1.z);
        a[1][3] = fmaxf(a[1][3], s0 + u1.w);
        a[2][0] = fmaxf(a[2][0], s0 + u2.x);
        a[2][1] = fmaxf(a[2][1], s0 + u2.y);
        a[2][2] = fmaxf(a[2][2], s0 + u2.z);
        a[2][3] = fmaxf(a[2][3], s0 + u2.w);
        a[3][0] = fmaxf(a[3][0], s0 + u3.x);
        a[3][1] = fmaxf(a[3][1], s0 + u3.y);
        a[3][2] = fmaxf(a[3][2], s0 + u3.z);
        a[3][3] = fmaxf(a[3][3], s0 + u3.w);
        a[0][0] = fmaxf(a[0][0], s1 + w0.x);
        a[0][1] = fmaxf(a[0][1], s1 + w0.y);
        a[0][2] = fmaxf(a[0][2], s1 + w0.z);
        a[0][3] = fmaxf(a[0][3], s1 + w0.w);
        a[1][0] = fmaxf(a[1][0], s1 + w1.x);
        a[1][1] = fmaxf(a[1][1], s1 + w1.y);
        a[1][2] = fmaxf(a[1][2], s1 + w1.z);
        a[1][3] = fmaxf(a[1][3], s1 + w1.w);
        a[2][0] = fmaxf(a[2][0], s1 + w2.x);
        a[2][1] = fmaxf(a[2][1], s1 + w2.y);
        a[2][2] = fmaxf(a[2][2], s1 + w2.z);
        a[2][3] = fmaxf(a[2][3], s1 + w2.w);
        a[3][0] = fmaxf(a[3][0], s1 + w3.x);
        a[3][1] = fmaxf(a[3][1], s1 + w3.y);
        a[3][2] = fmaxf(a[3][2], s1 + w3.z);
        a[3][3] = fmaxf(a[3][3], s1 + w3.w);
    }

    // Certificate (decode cmax) + global queue push + tropical bias + store.
    float* orow = out + (size_t)b * Fn;
    #pragma unroll
    for (int c = 0; c < 4; c++) {
        const int i = h * 512 + c * 128 + lane * 4;
        uint4 cme = *(const uint4*)(g_cmax_enc + i);
        const float th[4] = {TAU + dec_f(cme.x), TAU + dec_f(cme.y),
                             TAU + dec_f(cme.z), TAU + dec_f(cme.w)};
        #pragma unroll
        for (int e = 0; e < 4; e++) {
            if (a[c][e] < th[e]) {
                int qp = atomicAdd(&g_qcnt, 1);
                if (qp < QCAP) g_queue[qp] = b * Fn + (i + e);
            }
        }
        float4 bb = *(const float4*)(bias + i);
        *(float4*)(orow + i) = make_float4(fmaxf(a[c][0], bb.x),
                                           fmaxf(a[c][1], bb.y),
                                           fmaxf(a[c][2], bb.z),
                                           fmaxf(a[c][3], bb.w));
    }
}

// ---------------------------------------------------------------------------
// Kernel 3: exact cleanup. One warp per queued element; lane-parallel scan.
// ---------------------------------------------------------------------------
__global__ __launch_bounds__(128) void cleanup_kernel(
    const float* __restrict__ W,
    const float* __restrict__ bias,
    float* __restrict__ out)
{
    const int lane  = threadIdx.x & 31;
    const int warpg = (blockIdx.x * blockDim.x + threadIdx.x) >> 5;
    const int nwarp = (gridDim.x * blockDim.x) >> 5;
    const int qn    = min(g_qcnt, QCAP);

    for (int e = warpg; e < qn; e += nwarp) {
        const int idx = g_queue[e];
        const int b = idx >> 10, i = idx & (Fn - 1);
        const float* xrow = g_xn + (size_t)b * Fn;
        const float* wc   = W + i;
        float m = -INFINITY;
        for (int k = lane; k < Fn; k += 32)
            m = fmaxf(m, xrow[k] + wc[(size_t)k * Fn]);
        #pragma unroll
        for (int o = 16; o > 0; o >>= 1)
            m = fmaxf(m, __shfl_xor_sync(0xFFFFFFFFu, m, o));
        if (lane == 0)
            out[idx] = fmaxf(m, bias[i]);
    }
}

// ---------------------------------------------------------------------------
extern "C" void kernel_launch(void* const* d_in, const int* in_sizes, int n_in,
                              void* d_out, int out_size)
{
    const float* x     = (const float*)d_in[0];
    const float* W     = (const float*)d_in[1];
    const float* bvec  = (const float*)d_in[2];
    const float* gamma = (const float*)d_in[3];
    const float* beta  = (const float*)d_in[4];
    float* out = (float*)d_out;

    prep_kernel<<<Bn + 128, 256>>>(x, W, gamma, beta);
    tropical_kernel<<<Bn / 4, 256>>>(W, bvec, out);
    cleanup_kernel<<<2048, 128>>>(W, bvec, out);
}